// round 12
// baseline (speedup 1.0000x reference)
#include <cuda_runtime.h>
#include <cuda_fp16.h>
#include <math.h>
#include <stdint.h>

#define NN 4096
#define IN_DIM 512
#define OUT_DIM 512
#define HEADS 4
#define DK 128
#define KT 64
#define S 36                       // swh row stride (words) = 144B
#define WH_W (128 * S)
#define WH_BYTES (WH_W * 4)
#define FRAG_W (16 * 32 * 4)
#define LOG2E 1.4426950408889634f

// gemm smem geometry
#define GA_S 36
#define GB_S 132
#define GA_W (128 * GA_S)
#define GB_W (32 * GB_S)
#define GBUF_W (GA_W + GB_W)

// ---------------- scratch ----------------
__device__ float    g_Wh[NN * OUT_DIM];
__device__ __half   g_WhT2[OUT_DIM * NN];     // [d'][j] fp16
__device__ uint32_t g_Amask[NN * (NN / 32)];
__device__ float    g_slT[HEADS * NN];        // *LOG2E
__device__ float    g_srT[HEADS * NN];        // *LOG2E fp32
__device__ __half   g_srT2[HEADS * NN];       // *LOG2E fp16
__device__ float    g_srH4[NN * HEADS];       // *LOG2E, [j][h] interleaved
__device__ float    g_MT[HEADS * NN];

__device__ __forceinline__ float lrelu(float x) { return fmaxf(x, 0.2f * x); }
__device__ __forceinline__ float tf32r(float v) {
    uint32_t r;
    asm("cvt.rn.tf32.f32 %0, %1;" : "=r"(r) : "f"(v));
    return __uint_as_float(r);
}
__device__ __forceinline__ void cp16(uint32_t saddr, const void* g) {
    asm volatile("cp.async.ca.shared.global [%0], [%1], 16;" :: "r"(saddr), "l"(g));
}
__device__ __forceinline__ void cp_commit() {
    asm volatile("cp.async.commit_group;");
}
__device__ __forceinline__ void cp_wait0() {
    asm volatile("cp.async.wait_group 0;" ::: "memory");
}
__device__ __forceinline__ void mma_tf32(float* c, uint32_t a0, uint32_t a1,
                                         uint32_t a2, uint32_t a3,
                                         uint32_t b0, uint32_t b1) {
    asm volatile(
        "mma.sync.aligned.m16n8k8.row.col.f32.tf32.tf32.f32 "
        "{%0,%1,%2,%3}, {%4,%5,%6,%7}, {%8,%9}, {%0,%1,%2,%3};"
        : "+f"(c[0]), "+f"(c[1]), "+f"(c[2]), "+f"(c[3])
        : "r"(a0), "r"(a1), "r"(a2), "r"(a3), "r"(b0), "r"(b1));
}
__device__ __forceinline__ void mma16816(float* c, uint32_t a0, uint32_t a1,
                                         uint32_t a2, uint32_t a3,
                                         uint32_t b0, uint32_t b1) {
    asm volatile(
        "mma.sync.aligned.m16n8k16.row.col.f32.f16.f16.f32 "
        "{%0,%1,%2,%3}, {%4,%5,%6,%7}, {%8,%9}, {%0,%1,%2,%3};"
        : "+f"(c[0]), "+f"(c[1]), "+f"(c[2]), "+f"(c[3])
        : "r"(a0), "r"(a1), "r"(a2), "r"(a3), "r"(b0), "r"(b1));
}
__device__ __forceinline__ void ldsm4(uint32_t& r0, uint32_t& r1,
                                      uint32_t& r2, uint32_t& r3, uint32_t addr) {
    asm volatile("ldmatrix.sync.aligned.m8n8.x4.shared.b16 {%0,%1,%2,%3}, [%4];"
                 : "=r"(r0), "=r"(r1), "=r"(r2), "=r"(r3) : "r"(addr));
}
__device__ __forceinline__ uint64_t merge_mask(uint2 m, int gi, int jb) {
    uint64_t M = (uint64_t)m.x | ((uint64_t)m.y << 32);
    unsigned sc = (unsigned)(gi - jb);
    if (sc < 64u) M |= (1ull << sc);
    return M;
}
__device__ __forceinline__ uint32_t wcalc(__half2 sl2, __half2 nm2, __half2 sr2,
                                          uint32_t b0, uint32_t b1) {
    __half2 e = __hadd2(sl2, sr2);
    __half2 t = __hmul2(e, __float2half2_rn(0.2f));
    e = __hmax2(e, t);
    e = __hadd2(e, nm2);
    __half2 w = h2exp2(e);
    uint32_t m = (b0 ? 0x3C00u : 0u) | (b1 ? 0x3C000000u : 0u);
    __half2 mh = *reinterpret_cast<__half2*>(&m);
    w = __hmul2(w, mh);
    return *reinterpret_cast<uint32_t*>(&w);
}

// ---------------- Kernel A: Wh = H @ W via tf32 MMA (unchanged R11) ---------
__global__ void __launch_bounds__(256) gemm_kernel(const float* __restrict__ H,
                                                   const float* __restrict__ W,
                                                   float* __restrict__ Wh,
                                                   __half* __restrict__ WhT2) {
    extern __shared__ float gs[];
    const int t = threadIdx.x;
    const int wid = t >> 5, lane = t & 31;
    const int g = lane >> 2, tig = lane & 3;
    const int wm = wid & 3, wn = wid >> 2;
    const int rb = blockIdx.y * 128, cb = blockIdx.x * 128;

    float acc[2][8][4];
#pragma unroll
    for (int mt = 0; mt < 2; mt++)
#pragma unroll
        for (int nt = 0; nt < 8; nt++)
#pragma unroll
            for (int v = 0; v < 4; v++) acc[mt][nt][v] = 0.f;

    float4 ha[4], wb[4];
#pragma unroll
    for (int i = 0; i < 4; i++) {
        int f = t + i * 256;
        ha[i] = *reinterpret_cast<const float4*>(&H[(size_t)(rb + (f >> 3)) * IN_DIM + (f & 7) * 4]);
        wb[i] = *reinterpret_cast<const float4*>(&W[(size_t)(f >> 5) * OUT_DIM + cb + (f & 31) * 4]);
    }
    {
        float* sA = gs;
        float* sB = gs + GA_W;
#pragma unroll
        for (int i = 0; i < 4; i++) {
            int f = t + i * 256;
            float4 a = make_float4(tf32r(ha[i].x), tf32r(ha[i].y), tf32r(ha[i].z), tf32r(ha[i].w));
            float4 b = make_float4(tf32r(wb[i].x), tf32r(wb[i].y), tf32r(wb[i].z), tf32r(wb[i].w));
            *reinterpret_cast<float4*>(sA + (f >> 3) * GA_S + (f & 7) * 4) = a;
            *reinterpret_cast<float4*>(sB + (f >> 5) * GB_S + (f & 31) * 4) = b;
        }
    }
    __syncthreads();

    const int am0 = (wm * 32 + g) * GA_S;
    const int am1 = am0 + 8 * GA_S;
    const int bn = wn * 64 + g;

    for (int st = 0; st < IN_DIM / 32; st++) {
        if (st + 1 < IN_DIM / 32) {
            int kb = (st + 1) * 32;
#pragma unroll
            for (int i = 0; i < 4; i++) {
                int f = t + i * 256;
                ha[i] = *reinterpret_cast<const float4*>(
                    &H[(size_t)(rb + (f >> 3)) * IN_DIM + kb + (f & 7) * 4]);
                wb[i] = *reinterpret_cast<const float4*>(
                    &W[(size_t)(kb + (f >> 5)) * OUT_DIM + cb + (f & 31) * 4]);
            }
        }
        {
            const float* sA = gs + (st & 1) * GBUF_W;
            const float* sB = sA + GA_W;
#pragma unroll
            for (int ks = 0; ks < 4; ks++) {
                const int k0 = ks * 8 + tig;
                uint32_t a00 = __float_as_uint(sA[am0 + k0]);
                uint32_t a01 = __float_as_uint(sA[am1 + k0]);
                uint32_t a02 = __float_as_uint(sA[am0 + k0 + 4]);
                uint32_t a03 = __float_as_uint(sA[am1 + k0 + 4]);
                uint32_t a10 = __float_as_uint(sA[am0 + 16 * GA_S + k0]);
                uint32_t a11 = __float_as_uint(sA[am1 + 16 * GA_S + k0]);
                uint32_t a12 = __float_as_uint(sA[am0 + 16 * GA_S + k0 + 4]);
                uint32_t a13 = __float_as_uint(sA[am1 + 16 * GA_S + k0 + 4]);
#pragma unroll
                for (int nt = 0; nt < 8; nt++) {
                    uint32_t b0 = __float_as_uint(sB[k0 * GB_S + bn + nt * 8]);
                    uint32_t b1 = __float_as_uint(sB[(k0 + 4) * GB_S + bn + nt * 8]);
                    mma_tf32(acc[0][nt], a00, a01, a02, a03, b0, b1);
                    mma_tf32(acc[1][nt], a10, a11, a12, a13, b0, b1);
                }
            }
        }
        if (st + 1 < IN_DIM / 32) {
            float* sA = gs + ((st + 1) & 1) * GBUF_W;
            float* sB = sA + GA_W;
#pragma unroll
            for (int i = 0; i < 4; i++) {
                int f = t + i * 256;
                float4 a = make_float4(tf32r(ha[i].x), tf32r(ha[i].y), tf32r(ha[i].z), tf32r(ha[i].w));
                float4 b = make_float4(tf32r(wb[i].x), tf32r(wb[i].y), tf32r(wb[i].z), tf32r(wb[i].w));
                *reinterpret_cast<float4*>(sA + (f >> 3) * GA_S + (f & 7) * 4) = a;
                *reinterpret_cast<float4*>(sB + (f >> 5) * GB_S + (f & 31) * 4) = b;
            }
        }
        __syncthreads();
    }

#pragma unroll
    for (int mt = 0; mt < 2; mt++) {
        int row = rb + wm * 32 + mt * 16 + g;
#pragma unroll
        for (int nt = 0; nt < 8; nt++) {
            int col = cb + wn * 64 + nt * 8 + 2 * tig;
            float c0 = acc[mt][nt][0], c1 = acc[mt][nt][1];
            float c2 = acc[mt][nt][2], c3 = acc[mt][nt][3];
            *reinterpret_cast<float2*>(&Wh[(size_t)row * OUT_DIM + col]) = make_float2(c0, c1);
            *reinterpret_cast<float2*>(&Wh[(size_t)(row + 8) * OUT_DIM + col]) = make_float2(c2, c3);
            WhT2[(size_t)col * NN + row]           = __float2half_rn(c0);
            WhT2[(size_t)(col + 1) * NN + row]     = __float2half_rn(c1);
            WhT2[(size_t)col * NN + row + 8]       = __float2half_rn(c2);
            WhT2[(size_t)(col + 1) * NN + row + 8] = __float2half_rn(c3);
        }
    }
}

// ---------------- Kernel B: sl/sr, prescaled; + head-interleaved copy -------
__global__ void score_kernel(const float* __restrict__ Wh,
                             const float* __restrict__ al,
                             const float* __restrict__ ar,
                             float* __restrict__ slT, float* __restrict__ srT,
                             __half* __restrict__ srT2,
                             float* __restrict__ srH4) {
    int i = blockIdx.x;
    int h = threadIdx.x >> 5;
    int lane = threadIdx.x & 31;
    float4 w = *reinterpret_cast<const float4*>(&Wh[(size_t)i * OUT_DIM + h * DK + lane * 4]);
    float4 l = *reinterpret_cast<const float4*>(&al[h * DK + lane * 4]);
    float4 r = *reinterpret_cast<const float4*>(&ar[h * DK + lane * 4]);
    float s1 = w.x * l.x + w.y * l.y + w.z * l.z + w.w * l.w;
    float s2 = w.x * r.x + w.y * r.y + w.z * r.z + w.w * r.w;
#pragma unroll
    for (int off = 16; off > 0; off >>= 1) {
        s1 += __shfl_xor_sync(0xFFFFFFFFu, s1, off);
        s2 += __shfl_xor_sync(0xFFFFFFFFu, s2, off);
    }
    if (lane == 0) {
        slT[h * NN + i] = s1 * LOG2E;
        srT[h * NN + i] = s2 * LOG2E;
        srT2[h * NN + i] = __float2half_rn(s2 * LOG2E);
        srH4[i * HEADS + h] = s2 * LOG2E;
    }
}

// ---------------- Kernel B2: branch-free row-max (vectorized) + bitmask -----
__global__ void __launch_bounds__(256) rowmax_kernel(const int* __restrict__ A,
                                                     const float* __restrict__ slT,
                                                     const float4* __restrict__ srH4,
                                                     float* __restrict__ MT,
                                                     uint32_t* __restrict__ Amask) {
    int i = blockIdx.x;
    int t = threadIdx.x;
    int w = t >> 5, lane = t & 31;
    const int* arow = A + (size_t)i * NN;
    float mx[HEADS];
#pragma unroll
    for (int h = 0; h < HEADS; h++) mx[h] = -INFINITY;
#pragma unroll 4
    for (int it = 0; it < NN / 256; it++) {
        int j = it * 256 + t;
        bool edge = arow[j] > 0;
        uint32_t bits = __ballot_sync(0xFFFFFFFFu, edge);
        if (lane == 0) Amask[i * (NN / 32) + it * 8 + w] = bits;
        float sel = (edge || (j == i)) ? 0.f : -INFINITY;
        float4 s = srH4[j];
        mx[0] = fmaxf(mx[0], s.x + sel);
        mx[1] = fmaxf(mx[1], s.y + sel);
        mx[2] = fmaxf(mx[2], s.z + sel);
        mx[3] = fmaxf(mx[3], s.w + sel);
    }
    __shared__ float red[HEADS][256];
#pragma unroll
    for (int h = 0; h < HEADS; h++) red[h][t] = mx[h];
    __syncthreads();
    for (int s = 128; s > 0; s >>= 1) {
        if (t < s) {
#pragma unroll
            for (int h = 0; h < HEADS; h++)
                red[h][t] = fmaxf(red[h][t], red[h][t + s]);
        }
        __syncthreads();
    }
    if (t < HEADS) {
        float e = slT[t * NN + i] + red[t][0];
        MT[t * NN + i] = lrelu(e);
    }
}

// ---------------- Kernel C: fp16 MMA attn + cp.async fills ------------------
__global__ void __launch_bounds__(256, 2) attn_kernel(const uint32_t* __restrict__ Amask,
                                                      const __half* __restrict__ WhT2,
                                                      const float* __restrict__ slT,
                                                      const __half* __restrict__ srT2,
                                                      const float* __restrict__ MT,
                                                      float* __restrict__ out) {
    extern __shared__ uint32_t dyn[];
    __shared__ __align__(16) __half ssr[NN];
    __shared__ __align__(16) uint32_t sfrag[2 * FRAG_W];
    __shared__ float ssl[64], sMx[64];

    const int h = blockIdx.y;
    const int rb = blockIdx.x * 64;
    const int t = threadIdx.x;
    const int wid = t >> 5, lane = t & 31;
    const int g = lane >> 2, tig = lane & 3;
    const int rg = wid >> 1;
    const int ch = wid & 1;
    const int nbase = ch * 64;

    {
        const uint4* s4 = reinterpret_cast<const uint4*>(srT2 + (size_t)h * NN);
#pragma unroll
        for (int i = 0; i < 2; i++) {
            int idx = t + i * 256;
            reinterpret_cast<uint4*>(ssr)[idx] = s4[idx];
        }
    }
    if (t < 64) {
        ssl[t] = slT[h * NN + rb + t];
        sMx[t] = MT[h * NN + rb + t];
    }
    __syncthreads();

    const int r0l = rg * 16 + g, r1l = r0l + 8;
    const int gi0 = rb + r0l, gi1 = rb + r1l;
    const __half2 sl2_0 = __float2half2_rn(ssl[r0l]);
    const __half2 sl2_1 = __float2half2_rn(ssl[r1l]);
    const __half2 nm2_0 = __float2half2_rn(-sMx[r0l]);
    const __half2 nm2_1 = __float2half2_rn(-sMx[r1l]);
    const uint4* WhT4 = reinterpret_cast<const uint4*>(WhT2);
    const uint32_t ob = (lane < 4) ? 0x3C003C00u : 0u;
    const uint32_t swh_addr = (uint32_t)__cvta_generic_to_shared(dyn);

    // per-thread cp.async fill slots: flat = t + i*256 -> (d, jw)
    uint32_t fill_dst[4];
    const __half* fill_src_row[4];
#pragma unroll
    for (int i = 0; i < 4; i++) {
        int flat = t + i * 256;
        int d = flat >> 3, jw = flat & 7;
        fill_dst[i] = swh_addr + (d * S + jw * 4) * 4;
        fill_src_row[i] = WhT2 + (size_t)(h * DK + d) * NN + jw * 8;
    }

    uint32_t ldsm_base[4];
#pragma unroll
    for (int p = 0; p < 4; p++) {
        int rowp = nbase + p * 16 + (lane & 7) + (((lane >> 4) & 1) << 3);
        ldsm_base[p] = swh_addr + rowp * (S * 4) + (((lane >> 3) & 1) << 4);
    }

    float acc[9][4];
#pragma unroll
    for (int nt = 0; nt < 9; nt++)
#pragma unroll
        for (int v = 0; v < 4; v++) acc[nt][v] = 0.f;

    uint2 nm0, nm1;

    // ---- prologue: cp.async fill tile 0 + frags tile 0 ----
    {
        nm0 = *reinterpret_cast<const uint2*>(Amask + (size_t)gi0 * (NN / 32));
        nm1 = *reinterpret_cast<const uint2*>(Amask + (size_t)gi1 * (NN / 32));
#pragma unroll
        for (int i = 0; i < 4; i++) cp16(fill_dst[i], fill_src_row[i]);
        cp_commit();
        uint64_t M0 = merge_mask(nm0, gi0, 0);
        uint64_t M1 = merge_mask(nm1, gi1, 0);
#pragma unroll
        for (int q = 0; q < 2; q++) {
            int kc = 2 * ch + q;
            int c0 = kc * 16 + 2 * tig;
            __half2 srA = *reinterpret_cast<const __half2*>(ssr + c0);
            __half2 srB = *reinterpret_cast<const __half2*>(ssr + c0 + 8);
            uint32_t s0 = (uint32_t)(M0 >> c0);
            uint32_t s1 = (uint32_t)(M1 >> c0);
            uint4 v;
            v.x = wcalc(sl2_0, nm2_0, srA, s0 & 1u, s0 & 2u);
            v.y = wcalc(sl2_1, nm2_1, srA, s1 & 1u, s1 & 2u);
            v.z = wcalc(sl2_0, nm2_0, srB, (s0 >> 8) & 1u, (s0 >> 8) & 2u);
            v.w = wcalc(sl2_1, nm2_1, srB, (s1 >> 8) & 1u, (s1 >> 8) & 2u);
            *reinterpret_cast<uint4*>(sfrag + ((rg * 4 + kc) * 32 + lane) * 4) = v;
        }
        cp_wait0();
    }
    __syncthreads();

    for (int jt = 0; jt < NN / KT; jt++) {
        // ---- issue cp.async fill for tile jt+1 (other buffer) + mask loads ----
        if (jt + 1 < NN / KT) {
            const uint32_t bufo = ((jt + 1) & 1) ? WH_BYTES : 0;
            const int jbn = (jt + 1) * KT;
            nm0 = *reinterpret_cast<const uint2*>(Amask + (size_t)gi0 * (NN / 32) + 2 * (jt + 1));
            nm1 = *reinterpret_cast<const uint2*>(Amask + (size_t)gi1 * (NN / 32) + 2 * (jt + 1));
#pragma unroll
            for (int i = 0; i < 4; i++)
                cp16(fill_dst[i] + bufo, fill_src_row[i] + jbn);
            cp_commit();
        }

        // ---- MMA phase (buffer jt&1) ----
        {
            const uint32_t* fsrc = sfrag + ((jt & 1) ? FRAG_W : 0);
            const uint32_t bo = (jt & 1) ? WH_BYTES : 0;
#pragma unroll
            for (int kc = 0; kc < 4; kc++) {
                uint4 av = *reinterpret_cast<const uint4*>(fsrc + ((rg * 4 + kc) * 32 + lane) * 4);
#pragma unroll
                for (int p = 0; p < 4; p++) {
                    uint32_t b0, b1, b2, b3;
                    ldsm4(b0, b1, b2, b3, ldsm_base[p] + bo + kc * 32);
                    mma16816(acc[2 * p], av.x, av.y, av.z, av.w, b0, b1);
                    mma16816(acc[2 * p + 1], av.x, av.y, av.z, av.w, b2, b3);
                }
                mma16816(acc[8], av.x, av.y, av.z, av.w, ob, ob);
            }
        }

        // ---- frags for jt+1 + wait fills ----
        if (jt + 1 < NN / KT) {
            const int jbn = (jt + 1) * KT;
            uint64_t M0 = merge_mask(nm0, gi0, jbn);
            uint64_t M1 = merge_mask(nm1, gi1, jbn);
            uint32_t* fdst = sfrag + (((jt + 1) & 1) ? FRAG_W : 0);
#pragma unroll
            for (int q = 0; q < 2; q++) {
                int kc = 2 * ch + q;
                int c0 = kc * 16 + 2 * tig;
                __half2 srA = *reinterpret_cast<const __half2*>(ssr + jbn + c0);
                __half2 srB = *reinterpret_cast<const __half2*>(ssr + jbn + c0 + 8);
                uint32_t s0 = (uint32_t)(M0 >> c0);
                uint32_t s1 = (uint32_t)(M1 >> c0);
                uint4 v;
                v.x = wcalc(sl2_0, nm2_0, srA, s0 & 1u, s0 & 2u);
                v.y = wcalc(sl2_1, nm2_1, srA, s1 & 1u, s1 & 2u);
                v.z = wcalc(sl2_0, nm2_0, srB, (s0 >> 8) & 1u, (s0 >> 8) & 2u);
                v.w = wcalc(sl2_1, nm2_1, srB, (s1 >> 8) & 1u, (s1 >> 8) & 2u);
                *reinterpret_cast<uint4*>(fdst + ((rg * 4 + kc) * 32 + lane) * 4) = v;
            }
            cp_wait0();
        }
        __syncthreads();
    }

    float ls0 = __shfl_sync(0xFFFFFFFFu, acc[8][0], lane & ~3);
    float ls1 = __shfl_sync(0xFFFFFFFFu, acc[8][2], lane & ~3);
    const float inv0 = 1.f / ls0;
    const float inv1 = 1.f / ls1;

    const int row0 = rb + r0l, row1 = rb + r1l;
#pragma unroll
    for (int nt = 0; nt < 8; nt++) {
        int col = h * DK + nbase + nt * 8 + 2 * tig;
        float x0 = acc[nt][0] * inv0, x1 = acc[nt][1] * inv0;
        float y0 = acc[nt][2] * inv1, y1 = acc[nt][3] * inv1;
        float2 o0, o1;
        o0.x = x0 > 0.f ? x0 : (__expf(x0) - 1.f);
        o0.y = x1 > 0.f ? x1 : (__expf(x1) - 1.f);
        o1.x = y0 > 0.f ? y0 : (__expf(y0) - 1.f);
        o1.y = y1 > 0.f ? y1 : (__expf(y1) - 1.f);
        *reinterpret_cast<float2*>(&out[(size_t)row0 * OUT_DIM + col]) = o0;
        *reinterpret_cast<float2*>(&out[(size_t)row1 * OUT_DIM + col]) = o1;
    }
}

// ---------------- launch ----------------
extern "C" void kernel_launch(void* const* d_in, const int* in_sizes, int n_in,
                              void* d_out, int out_size) {
    const float* H  = (const float*)d_in[0];
    const int*   A  = (const int*)  d_in[1];
    const float* W  = (const float*)d_in[2];
    const float* al = (const float*)d_in[3];
    const float* ar = (const float*)d_in[4];
    float* out = (float*)d_out;

    float*    Wh;    cudaGetSymbolAddress((void**)&Wh,    g_Wh);
    __half*   WhT2;  cudaGetSymbolAddress((void**)&WhT2,  g_WhT2);
    uint32_t* Amask; cudaGetSymbolAddress((void**)&Amask, g_Amask);
    float*    slT;   cudaGetSymbolAddress((void**)&slT,   g_slT);
    float*    srT;   cudaGetSymbolAddress((void**)&srT,   g_srT);
    __half*   srT2;  cudaGetSymbolAddress((void**)&srT2,  g_srT2);
    float*    srH4;  cudaGetSymbolAddress((void**)&srH4,  g_srH4);
    float*    MT;    cudaGetSymbolAddress((void**)&MT,    g_MT);

    const int gemm_smem = 2 * GBUF_W * 4;
    cudaFuncSetAttribute(gemm_kernel, cudaFuncAttributeMaxDynamicSharedMemorySize, gemm_smem);
    dim3 gA(OUT_DIM / 128, NN / 128);
    gemm_kernel<<<gA, 256, gemm_smem>>>(H, W, Wh, WhT2);

    score_kernel<<<NN, 128>>>(Wh, al, ar, slT, srT, srT2, srH4);

    rowmax_kernel<<<NN, 256>>>(A, slT, (const float4*)srH4, MT, Amask);

    const int dyn_bytes = 2 * WH_BYTES;
    cudaFuncSetAttribute(attn_kernel, cudaFuncAttributeMaxDynamicSharedMemorySize, dyn_bytes);
    dim3 gC(NN / 64, HEADS);
    attn_kernel<<<gC, 256, dyn_bytes>>>(Amask, WhT2, slT, srT2, MT, out);
}

// round 16
// speedup vs baseline: 1.0445x; 1.0445x over previous
#include <cuda_runtime.h>
#include <cuda_fp16.h>
#include <math.h>
#include <stdint.h>

#define NN 4096
#define IN_DIM 512
#define OUT_DIM 512
#define HEADS 4
#define DK 128
#define KT 64
#define S 36                       // swh row stride (words) = 144B
#define WH_W (128 * S)
#define WH_BYTES (WH_W * 4)
#define FRAG_W (16 * 32 * 4)
#define LOG2E 1.4426950408889634f

// gemm smem geometry
#define GA_S 36
#define GB_S 132
#define GA_W (128 * GA_S)
#define GB_W (32 * GB_S)
#define GBUF_W (GA_W + GB_W)

// ---------------- scratch ----------------
__device__ __half   g_WhT2[OUT_DIM * NN];     // [d'][j] fp16
__device__ uint32_t g_Amask[NN * (NN / 32)];
__device__ float    g_slT[HEADS * NN];        // *LOG2E
__device__ float    g_srT[HEADS * NN];        // *LOG2E fp32
__device__ __half   g_srT2[HEADS * NN];       // *LOG2E fp16
__device__ float    g_srH4[NN * HEADS];       // *LOG2E, [j][h]
__device__ float    g_MT[HEADS * NN];

__device__ __forceinline__ float lrelu(float x) { return fmaxf(x, 0.2f * x); }
__device__ __forceinline__ float tf32r(float v) {
    uint32_t r;
    asm("cvt.rn.tf32.f32 %0, %1;" : "=r"(r) : "f"(v));
    return __uint_as_float(r);
}
__device__ __forceinline__ void cp16(uint32_t saddr, const void* g) {
    asm volatile("cp.async.ca.shared.global [%0], [%1], 16;" :: "r"(saddr), "l"(g));
}
__device__ __forceinline__ void cp_commit() {
    asm volatile("cp.async.commit_group;");
}
__device__ __forceinline__ void cp_wait0() {
    asm volatile("cp.async.wait_group 0;" ::: "memory");
}
__device__ __forceinline__ void mma_tf32(float* c, uint32_t a0, uint32_t a1,
                                         uint32_t a2, uint32_t a3,
                                         uint32_t b0, uint32_t b1) {
    asm volatile(
        "mma.sync.aligned.m16n8k8.row.col.f32.tf32.tf32.f32 "
        "{%0,%1,%2,%3}, {%4,%5,%6,%7}, {%8,%9}, {%0,%1,%2,%3};"
        : "+f"(c[0]), "+f"(c[1]), "+f"(c[2]), "+f"(c[3])
        : "r"(a0), "r"(a1), "r"(a2), "r"(a3), "r"(b0), "r"(b1));
}
__device__ __forceinline__ void mma16816(float* c, uint32_t a0, uint32_t a1,
                                         uint32_t a2, uint32_t a3,
                                         uint32_t b0, uint32_t b1) {
    asm volatile(
        "mma.sync.aligned.m16n8k16.row.col.f32.f16.f16.f32 "
        "{%0,%1,%2,%3}, {%4,%5,%6,%7}, {%8,%9}, {%0,%1,%2,%3};"
        : "+f"(c[0]), "+f"(c[1]), "+f"(c[2]), "+f"(c[3])
        : "r"(a0), "r"(a1), "r"(a2), "r"(a3), "r"(b0), "r"(b1));
}
__device__ __forceinline__ void ldsm4(uint32_t& r0, uint32_t& r1,
                                      uint32_t& r2, uint32_t& r3, uint32_t addr) {
    asm volatile("ldmatrix.sync.aligned.m8n8.x4.shared.b16 {%0,%1,%2,%3}, [%4];"
                 : "=r"(r0), "=r"(r1), "=r"(r2), "=r"(r3) : "r"(addr));
}
__device__ __forceinline__ uint64_t merge_mask(uint2 m, int gi, int jb) {
    uint64_t M = (uint64_t)m.x | ((uint64_t)m.y << 32);
    unsigned sc = (unsigned)(gi - jb);
    if (sc < 64u) M |= (1ull << sc);
    return M;
}
__device__ __forceinline__ uint32_t wcalc(__half2 sl2, __half2 nm2, __half2 sr2,
                                          uint32_t b0, uint32_t b1) {
    __half2 e = __hadd2(sl2, sr2);
    __half2 t = __hmul2(e, __float2half2_rn(0.2f));
    e = __hmax2(e, t);
    e = __hadd2(e, nm2);
    __half2 w = h2exp2(e);
    uint32_t m = (b0 ? 0x3C00u : 0u) | (b1 ? 0x3C000000u : 0u);
    __half2 mh = *reinterpret_cast<__half2*>(&m);
    w = __hmul2(w, mh);
    return *reinterpret_cast<uint32_t*>(&w);
}

// ---------------- Kernel A: Wh=H@W tf32 MMA, fused scores + WhT2 ------------
// grid (4, 32): blockIdx.x == head. Epilogue computes sl/sr in-CTA and writes
// slT/srT/srT2/srH4 directly (score kernel eliminated; Wh never materialized).
__global__ void __launch_bounds__(256) gemm_kernel(const float* __restrict__ H,
                                                   const float* __restrict__ W,
                                                   const float* __restrict__ al,
                                                   const float* __restrict__ ar,
                                                   __half* __restrict__ WhT2,
                                                   float* __restrict__ slT,
                                                   float* __restrict__ srT,
                                                   __half* __restrict__ srT2,
                                                   float* __restrict__ srH4) {
    extern __shared__ float gs[];
    const int t = threadIdx.x;
    const int wid = t >> 5, lane = t & 31;
    const int g = lane >> 2, tig = lane & 3;
    const int wm = wid & 3, wn = wid >> 2;
    const int rb = blockIdx.y * 128, cb = blockIdx.x * 128;

    float acc[2][8][4];
#pragma unroll
    for (int mt = 0; mt < 2; mt++)
#pragma unroll
        for (int nt = 0; nt < 8; nt++)
#pragma unroll
            for (int v = 0; v < 4; v++) acc[mt][nt][v] = 0.f;

    float4 ha[4], wb[4];
#pragma unroll
    for (int i = 0; i < 4; i++) {
        int f = t + i * 256;
        ha[i] = *reinterpret_cast<const float4*>(&H[(size_t)(rb + (f >> 3)) * IN_DIM + (f & 7) * 4]);
        wb[i] = *reinterpret_cast<const float4*>(&W[(size_t)(f >> 5) * OUT_DIM + cb + (f & 31) * 4]);
    }
    {
        float* sA = gs;
        float* sB = gs + GA_W;
#pragma unroll
        for (int i = 0; i < 4; i++) {
            int f = t + i * 256;
            float4 a = make_float4(tf32r(ha[i].x), tf32r(ha[i].y), tf32r(ha[i].z), tf32r(ha[i].w));
            float4 b = make_float4(tf32r(wb[i].x), tf32r(wb[i].y), tf32r(wb[i].z), tf32r(wb[i].w));
            *reinterpret_cast<float4*>(sA + (f >> 3) * GA_S + (f & 7) * 4) = a;
            *reinterpret_cast<float4*>(sB + (f >> 5) * GB_S + (f & 31) * 4) = b;
        }
    }
    __syncthreads();

    const int am0 = (wm * 32 + g) * GA_S;
    const int am1 = am0 + 8 * GA_S;
    const int bn = wn * 64 + g;

    for (int st = 0; st < IN_DIM / 32; st++) {
        if (st + 1 < IN_DIM / 32) {
            int kb = (st + 1) * 32;
#pragma unroll
            for (int i = 0; i < 4; i++) {
                int f = t + i * 256;
                ha[i] = *reinterpret_cast<const float4*>(
                    &H[(size_t)(rb + (f >> 3)) * IN_DIM + kb + (f & 7) * 4]);
                wb[i] = *reinterpret_cast<const float4*>(
                    &W[(size_t)(kb + (f >> 5)) * OUT_DIM + cb + (f & 31) * 4]);
            }
        }
        {
            const float* sA = gs + (st & 1) * GBUF_W;
            const float* sB = sA + GA_W;
#pragma unroll
            for (int ks = 0; ks < 4; ks++) {
                const int k0 = ks * 8 + tig;
                uint32_t a00 = __float_as_uint(sA[am0 + k0]);
                uint32_t a01 = __float_as_uint(sA[am1 + k0]);
                uint32_t a02 = __float_as_uint(sA[am0 + k0 + 4]);
                uint32_t a03 = __float_as_uint(sA[am1 + k0 + 4]);
                uint32_t a10 = __float_as_uint(sA[am0 + 16 * GA_S + k0]);
                uint32_t a11 = __float_as_uint(sA[am1 + 16 * GA_S + k0]);
                uint32_t a12 = __float_as_uint(sA[am0 + 16 * GA_S + k0 + 4]);
                uint32_t a13 = __float_as_uint(sA[am1 + 16 * GA_S + k0 + 4]);
#pragma unroll
                for (int nt = 0; nt < 8; nt++) {
                    uint32_t b0 = __float_as_uint(sB[k0 * GB_S + bn + nt * 8]);
                    uint32_t b1 = __float_as_uint(sB[(k0 + 4) * GB_S + bn + nt * 8]);
                    mma_tf32(acc[0][nt], a00, a01, a02, a03, b0, b1);
                    mma_tf32(acc[1][nt], a10, a11, a12, a13, b0, b1);
                }
            }
        }
        if (st + 1 < IN_DIM / 32) {
            float* sA = gs + ((st + 1) & 1) * GBUF_W;
            float* sB = sA + GA_W;
#pragma unroll
            for (int i = 0; i < 4; i++) {
                int f = t + i * 256;
                float4 a = make_float4(tf32r(ha[i].x), tf32r(ha[i].y), tf32r(ha[i].z), tf32r(ha[i].w));
                float4 b = make_float4(tf32r(wb[i].x), tf32r(wb[i].y), tf32r(wb[i].z), tf32r(wb[i].w));
                *reinterpret_cast<float4*>(sA + (f >> 3) * GA_S + (f & 7) * 4) = a;
                *reinterpret_cast<float4*>(sB + (f >> 5) * GB_S + (f & 31) * 4) = b;
            }
        }
        __syncthreads();
    }

    // ---- epilogue 1: WhT2 fp16 stores ----
#pragma unroll
    for (int mt = 0; mt < 2; mt++) {
        int row = rb + wm * 32 + mt * 16 + g;
#pragma unroll
        for (int nt = 0; nt < 8; nt++) {
            int col = cb + wn * 64 + nt * 8 + 2 * tig;
            WhT2[(size_t)col * NN + row]           = __float2half_rn(acc[mt][nt][0]);
            WhT2[(size_t)(col + 1) * NN + row]     = __float2half_rn(acc[mt][nt][1]);
            WhT2[(size_t)col * NN + row + 8]       = __float2half_rn(acc[mt][nt][2]);
            WhT2[(size_t)(col + 1) * NN + row + 8] = __float2half_rn(acc[mt][nt][3]);
        }
    }

    // ---- epilogue 2: fused sl/sr (this CTA covers head blockIdx.x fully) ----
    float s1[2][2] = {{0.f, 0.f}, {0.f, 0.f}};
    float s2[2][2] = {{0.f, 0.f}, {0.f, 0.f}};
#pragma unroll
    for (int nt = 0; nt < 8; nt++) {
        int col = cb + wn * 64 + nt * 8 + 2 * tig;
        float a0 = al[col], a1 = al[col + 1];
        float r0 = ar[col], r1 = ar[col + 1];
#pragma unroll
        for (int mt = 0; mt < 2; mt++) {
            s1[mt][0] += acc[mt][nt][0] * a0 + acc[mt][nt][1] * a1;
            s1[mt][1] += acc[mt][nt][2] * a0 + acc[mt][nt][3] * a1;
            s2[mt][0] += acc[mt][nt][0] * r0 + acc[mt][nt][1] * r1;
            s2[mt][1] += acc[mt][nt][2] * r0 + acc[mt][nt][3] * r1;
        }
    }
#pragma unroll
    for (int off = 1; off <= 2; off <<= 1) {
#pragma unroll
        for (int mt = 0; mt < 2; mt++)
#pragma unroll
            for (int k = 0; k < 2; k++) {
                s1[mt][k] += __shfl_xor_sync(0xFFFFFFFFu, s1[mt][k], off);
                s2[mt][k] += __shfl_xor_sync(0xFFFFFFFFu, s2[mt][k], off);
            }
    }
    // cross-half (wn) reduce via 1KB of gs, then write all 4 score buffers
    float2* sred = reinterpret_cast<float2*>(gs);
    if (wn == 0 && tig == 0) {
#pragma unroll
        for (int mt = 0; mt < 2; mt++)
#pragma unroll
            for (int k = 0; k < 2; k++) {
                int rl = wm * 32 + mt * 16 + k * 8 + g;
                sred[rl * 2]     = make_float2(s1[mt][k], s2[mt][k]);
            }
    }
    __syncthreads();
    if (wn == 1 && tig == 0) {
        const int h = blockIdx.x;
#pragma unroll
        for (int mt = 0; mt < 2; mt++)
#pragma unroll
            for (int k = 0; k < 2; k++) {
                int rl = wm * 32 + mt * 16 + k * 8 + g;
                float2 p = sred[rl * 2];
                float S1 = (s1[mt][k] + p.x) * LOG2E;
                float S2 = (s2[mt][k] + p.y) * LOG2E;
                int row = rb + rl;
                slT[h * NN + row] = S1;
                srT[h * NN + row] = S2;
                srT2[h * NN + row] = __float2half_rn(S2);
                srH4[row * HEADS + h] = S2;
            }
    }
}

// ---------------- Kernel B2: branch-free row-max (vectorized) + bitmask -----
__global__ void __launch_bounds__(256) rowmax_kernel(const int* __restrict__ A,
                                                     const float* __restrict__ slT,
                                                     const float4* __restrict__ srH4,
                                                     float* __restrict__ MT,
                                                     uint32_t* __restrict__ Amask) {
    int i = blockIdx.x;
    int t = threadIdx.x;
    int w = t >> 5, lane = t & 31;
    const int* arow = A + (size_t)i * NN;
    float mx[HEADS];
#pragma unroll
    for (int h = 0; h < HEADS; h++) mx[h] = -INFINITY;
#pragma unroll 4
    for (int it = 0; it < NN / 256; it++) {
        int j = it * 256 + t;
        bool edge = arow[j] > 0;
        uint32_t bits = __ballot_sync(0xFFFFFFFFu, edge);
        if (lane == 0) Amask[i * (NN / 32) + it * 8 + w] = bits;
        float sel = (edge || (j == i)) ? 0.f : -INFINITY;
        float4 s = srH4[j];
        mx[0] = fmaxf(mx[0], s.x + sel);
        mx[1] = fmaxf(mx[1], s.y + sel);
        mx[2] = fmaxf(mx[2], s.z + sel);
        mx[3] = fmaxf(mx[3], s.w + sel);
    }
    __shared__ float red[HEADS][256];
#pragma unroll
    for (int h = 0; h < HEADS; h++) red[h][t] = mx[h];
    __syncthreads();
    for (int s = 128; s > 0; s >>= 1) {
        if (t < s) {
#pragma unroll
            for (int h = 0; h < HEADS; h++)
                red[h][t] = fmaxf(red[h][t], red[h][t + s]);
        }
        __syncthreads();
    }
    if (t < HEADS) {
        float e = slT[t * NN + i] + red[t][0];
        MT[t * NN + i] = lrelu(e);
    }
}

// ---------------- Kernel C: fp16 MMA attn (byte-identical to R12) -----------
__global__ void __launch_bounds__(256, 2) attn_kernel(const uint32_t* __restrict__ Amask,
                                                      const __half* __restrict__ WhT2,
                                                      const float* __restrict__ slT,
                                                      const __half* __restrict__ srT2,
                                                      const float* __restrict__ MT,
                                                      float* __restrict__ out) {
    extern __shared__ uint32_t dyn[];
    __shared__ __align__(16) __half ssr[NN];
    __shared__ __align__(16) uint32_t sfrag[2 * FRAG_W];
    __shared__ float ssl[64], sMx[64];

    const int h = blockIdx.y;
    const int rb = blockIdx.x * 64;
    const int t = threadIdx.x;
    const int wid = t >> 5, lane = t & 31;
    const int g = lane >> 2, tig = lane & 3;
    const int rg = wid >> 1;
    const int ch = wid & 1;
    const int nbase = ch * 64;

    {
        const uint4* s4 = reinterpret_cast<const uint4*>(srT2 + (size_t)h * NN);
#pragma unroll
        for (int i = 0; i < 2; i++) {
            int idx = t + i * 256;
            reinterpret_cast<uint4*>(ssr)[idx] = s4[idx];
        }
    }
    if (t < 64) {
        ssl[t] = slT[h * NN + rb + t];
        sMx[t] = MT[h * NN + rb + t];
    }
    __syncthreads();

    const int r0l = rg * 16 + g, r1l = r0l + 8;
    const int gi0 = rb + r0l, gi1 = rb + r1l;
    const __half2 sl2_0 = __float2half2_rn(ssl[r0l]);
    const __half2 sl2_1 = __float2half2_rn(ssl[r1l]);
    const __half2 nm2_0 = __float2half2_rn(-sMx[r0l]);
    const __half2 nm2_1 = __float2half2_rn(-sMx[r1l]);
    const uint32_t ob = (lane < 4) ? 0x3C003C00u : 0u;
    const uint32_t swh_addr = (uint32_t)__cvta_generic_to_shared(dyn);

    uint32_t fill_dst[4];
    const __half* fill_src_row[4];
#pragma unroll
    for (int i = 0; i < 4; i++) {
        int flat = t + i * 256;
        int d = flat >> 3, jw = flat & 7;
        fill_dst[i] = swh_addr + (d * S + jw * 4) * 4;
        fill_src_row[i] = WhT2 + (size_t)(h * DK + d) * NN + jw * 8;
    }

    uint32_t ldsm_base[4];
#pragma unroll
    for (int p = 0; p < 4; p++) {
        int rowp = nbase + p * 16 + (lane & 7) + (((lane >> 4) & 1) << 3);
        ldsm_base[p] = swh_addr + rowp * (S * 4) + (((lane >> 3) & 1) << 4);
    }

    float acc[9][4];
#pragma unroll
    for (int nt = 0; nt < 9; nt++)
#pragma unroll
        for (int v = 0; v < 4; v++) acc[nt][v] = 0.f;

    uint2 nm0, nm1;

    {
        nm0 = *reinterpret_cast<const uint2*>(Amask + (size_t)gi0 * (NN / 32));
        nm1 = *reinterpret_cast<const uint2*>(Amask + (size_t)gi1 * (NN / 32));
#pragma unroll
        for (int i = 0; i < 4; i++) cp16(fill_dst[i], fill_src_row[i]);
        cp_commit();
        uint64_t M0 = merge_mask(nm0, gi0, 0);
        uint64_t M1 = merge_mask(nm1, gi1, 0);
#pragma unroll
        for (int q = 0; q < 2; q++) {
            int kc = 2 * ch + q;
            int c0 = kc * 16 + 2 * tig;
            __half2 srA = *reinterpret_cast<const __half2*>(ssr + c0);
            __half2 srB = *reinterpret_cast<const __half2*>(ssr + c0 + 8);
            uint32_t s0 = (uint32_t)(M0 >> c0);
            uint32_t s1 = (uint32_t)(M1 >> c0);
            uint4 v;
            v.x = wcalc(sl2_0, nm2_0, srA, s0 & 1u, s0 & 2u);
            v.y = wcalc(sl2_1, nm2_1, srA, s1 & 1u, s1 & 2u);
            v.z = wcalc(sl2_0, nm2_0, srB, (s0 >> 8) & 1u, (s0 >> 8) & 2u);
            v.w = wcalc(sl2_1, nm2_1, srB, (s1 >> 8) & 1u, (s1 >> 8) & 2u);
            *reinterpret_cast<uint4*>(sfrag + ((rg * 4 + kc) * 32 + lane) * 4) = v;
        }
        cp_wait0();
    }
    __syncthreads();

    for (int jt = 0; jt < NN / KT; jt++) {
        if (jt + 1 < NN / KT) {
            const uint32_t bufo = ((jt + 1) & 1) ? WH_BYTES : 0;
            const int jbn = (jt + 1) * KT;
            nm0 = *reinterpret_cast<const uint2*>(Amask + (size_t)gi0 * (NN / 32) + 2 * (jt + 1));
            nm1 = *reinterpret_cast<const uint2*>(Amask + (size_t)gi1 * (NN / 32) + 2 * (jt + 1));
#pragma unroll
            for (int i = 0; i < 4; i++)
                cp16(fill_dst[i] + bufo, fill_src_row[i] + jbn);
            cp_commit();
        }
        {
            const uint32_t* fsrc = sfrag + ((jt & 1) ? FRAG_W : 0);
            const uint32_t bo = (jt & 1) ? WH_BYTES : 0;
#pragma unroll
            for (int kc = 0; kc < 4; kc++) {
                uint4 av = *reinterpret_cast<const uint4*>(fsrc + ((rg * 4 + kc) * 32 + lane) * 4);
#pragma unroll
                for (int p = 0; p < 4; p++) {
                    uint32_t b0, b1, b2, b3;
                    ldsm4(b0, b1, b2, b3, ldsm_base[p] + bo + kc * 32);
                    mma16816(acc[2 * p], av.x, av.y, av.z, av.w, b0, b1);
                    mma16816(acc[2 * p + 1], av.x, av.y, av.z, av.w, b2, b3);
                }
                mma16816(acc[8], av.x, av.y, av.z, av.w, ob, ob);
            }
        }
        if (jt + 1 < NN / KT) {
            const int jbn = (jt + 1) * KT;
            uint64_t M0 = merge_mask(nm0, gi0, jbn);
            uint64_t M1 = merge_mask(nm1, gi1, jbn);
            uint32_t* fdst = sfrag + (((jt + 1) & 1) ? FRAG_W : 0);
#pragma unroll
            for (int q = 0; q < 2; q++) {
                int kc = 2 * ch + q;
                int c0 = kc * 16 + 2 * tig;
                __half2 srA = *reinterpret_cast<const __half2*>(ssr + jbn + c0);
                __half2 srB = *reinterpret_cast<const __half2*>(ssr + jbn + c0 + 8);
                uint32_t s0 = (uint32_t)(M0 >> c0);
                uint32_t s1 = (uint32_t)(M1 >> c0);
                uint4 v;
                v.x = wcalc(sl2_0, nm2_0, srA, s0 & 1u, s0 & 2u);
                v.y = wcalc(sl2_1, nm2_1, srA, s1 & 1u, s1 & 2u);
                v.z = wcalc(sl2_0, nm2_0, srB, (s0 >> 8) & 1u, (s0 >> 8) & 2u);
                v.w = wcalc(sl2_1, nm2_1, srB, (s1 >> 8) & 1u, (s1 >> 8) & 2u);
                *reinterpret_cast<uint4*>(fdst + ((rg * 4 + kc) * 32 + lane) * 4) = v;
            }
            cp_wait0();
        }
        __syncthreads();
    }

    float ls0 = __shfl_sync(0xFFFFFFFFu, acc[8][0], lane & ~3);
    float ls1 = __shfl_sync(0xFFFFFFFFu, acc[8][2], lane & ~3);
    const float inv0 = 1.f / ls0;
    const float inv1 = 1.f / ls1;

    const int row0 = rb + r0l, row1 = rb + r1l;
#pragma unroll
    for (int nt = 0; nt < 8; nt++) {
        int col = h * DK + nbase + nt * 8 + 2 * tig;
        float x0 = acc[nt][0] * inv0, x1 = acc[nt][1] * inv0;
        float y0 = acc[nt][2] * inv1, y1 = acc[nt][3] * inv1;
        float2 o0, o1;
        o0.x = x0 > 0.f ? x0 : (__expf(x0) - 1.f);
        o0.y = x1 > 0.f ? x1 : (__expf(x1) - 1.f);
        o1.x = y0 > 0.f ? y0 : (__expf(y0) - 1.f);
        o1.y = y1 > 0.f ? y1 : (__expf(y1) - 1.f);
        *reinterpret_cast<float2*>(&out[(size_t)row0 * OUT_DIM + col]) = o0;
        *reinterpret_cast<float2*>(&out[(size_t)row1 * OUT_DIM + col]) = o1;
    }
}

// ---------------- launch ----------------
extern "C" void kernel_launch(void* const* d_in, const int* in_sizes, int n_in,
                              void* d_out, int out_size) {
    const float* H  = (const float*)d_in[0];
    const int*   A  = (const int*)  d_in[1];
    const float* W  = (const float*)d_in[2];
    const float* al = (const float*)d_in[3];
    const float* ar = (const float*)d_in[4];
    float* out = (float*)d_out;

    __half*   WhT2;  cudaGetSymbolAddress((void**)&WhT2,  g_WhT2);
    uint32_t* Amask; cudaGetSymbolAddress((void**)&Amask, g_Amask);
    float*    slT;   cudaGetSymbolAddress((void**)&slT,   g_slT);
    float*    srT;   cudaGetSymbolAddress((void**)&srT,   g_srT);
    __half*   srT2;  cudaGetSymbolAddress((void**)&srT2,  g_srT2);
    float*    srH4;  cudaGetSymbolAddress((void**)&srH4,  g_srH4);
    float*    MT;    cudaGetSymbolAddress((void**)&MT,    g_MT);

    const int gemm_smem = 2 * GBUF_W * 4;
    cudaFuncSetAttribute(gemm_kernel, cudaFuncAttributeMaxDynamicSharedMemorySize, gemm_smem);
    dim3 gA(OUT_DIM / 128, NN / 128);
    gemm_kernel<<<gA, 256, gemm_smem>>>(H, W, al, ar, WhT2, slT, srT, srT2, srH4);

    rowmax_kernel<<<NN, 256>>>(A, slT, (const float4*)srH4, MT, Amask);

    const int dyn_bytes = 2 * WH_BYTES;
    cudaFuncSetAttribute(attn_kernel, cudaFuncAttributeMaxDynamicSharedMemorySize, dyn_bytes);
    dim3 gC(NN / 64, HEADS);
    attn_kernel<<<gC, 256, dyn_bytes>>>(Amask, WhT2, slT, srT2, MT, out);
}